// round 4
// baseline (speedup 1.0000x reference)
#include <cuda_runtime.h>
#include <cstdint>

#define BS   8
#define NN   1024
#define JJ   3
#define FIN  32
#define ROWS (BS*NN)        // 8192
#define RPC  16             // rows per CTA
#define NCTA (ROWS/RPC)     // 512
#define MT   64             // m per tile
#define NTILE (NN/MT)       // 16
#define WP2  194            // ws2 row stride in u64 (192 used); 2*194 % 32 == 4 -> banks 4r
#define XPAD 36             // xs row stride in floats (32 used)
#define WCPAD 98

typedef unsigned long long u64;

// scratch (no allocations allowed)
__device__ float g_zbuf[ROWS*64];
__device__ float g_part[NCTA*64];
__device__ float g_psq[NCTA*64];
__device__ float g_scale[64];
__device__ float g_shift[64];

__device__ __forceinline__ u64 pack2(float a, float b){
    u64 r; asm("mov.b64 %0,{%1,%2};" : "=l"(r) : "f"(a), "f"(b)); return r;
}
__device__ __forceinline__ void unpack2(u64 v, float& a, float& b){
    asm("mov.b64 {%0,%1},%2;" : "=f"(a), "=f"(b) : "l"(v));
}
__device__ __forceinline__ u64 fma2(u64 a, u64 b, u64 c){
    u64 d; asm("fma.rn.f32x2 %0,%1,%2,%3;" : "=l"(d) : "l"(a), "l"(b), "l"(c)); return d;
}

struct SmemA {                        // main loop
    u64   ws2[RPC*WP2];               // 24832 B : (w,w) pairs, [r][m*3+j]
    float xs[MT*XPAD];                // 9216 B  : [m][f] padded
};
struct SmemB {                        // epilogue
    float ys[RPC*96];                 // 6144 B
    float wc[64*WCPAD];               // 25088 B
    float bias[64];
    float psum[128];
    float psq[128];
};
union __align__(16) SmemU { SmemA a; SmemB b; };

__global__ __launch_bounds__(128, 4)
void k_main(const float* __restrict__ WW, const float* __restrict__ x,
            const float* __restrict__ W1, const float* __restrict__ b1,
            const float* __restrict__ W2, const float* __restrict__ b2)
{
    __shared__ SmemU sm;
    const int tid = threadIdx.x;
    const int cta = blockIdx.x;
    const int R0  = cta * RPC;
    const int b   = R0 / NN;

    // warp-uniform mh; lanes vary (r, fg) only -> conflict-free smem
    const int lane = tid & 31;
    const int warp = tid >> 5;
    const int fg = lane & 3;                  // f-group of 8
    const int mh = warp & 1;                  // m-PAIR parity (warp-uniform)
    const int r  = (lane >> 2) + (warp >> 1) * 8;   // 0..15

    u64 acc[3][4];
    #pragma unroll
    for (int j = 0; j < 3; j++)
        #pragma unroll
        for (int p = 0; p < 4; p++) acc[j][p] = 0ull;

    const float* xb = x + (size_t)b * NN * FIN;

    // tile-invariant global load assignments
    int w_rr[6], w_cc[6];
    #pragma unroll
    for (int k = 0; k < 6; k++) { int idx = tid + k*128; w_rr[k] = idx / 48; w_cc[k] = idx % 48; }
    int x_mm[4], x_cc[4];
    #pragma unroll
    for (int k = 0; k < 4; k++) { int idx = tid + k*128; x_mm[k] = idx >> 3; x_cc[k] = idx & 7; }

    float4 wreg[6], xreg[4];

    auto loadg = [&](int t){
        const int m0 = t * MT;
        #pragma unroll
        for (int k = 0; k < 6; k++) {
            const float4* wg = (const float4*)(WW + ((size_t)(R0 + w_rr[k]) * NN + m0) * JJ);
            wreg[k] = __ldg(&wg[w_cc[k]]);
        }
        #pragma unroll
        for (int k = 0; k < 4; k++) {
            const float4* xg = (const float4*)(xb + (size_t)(m0 + x_mm[k]) * FIN);
            xreg[k] = __ldg(&xg[x_cc[k]]);
        }
    };
    auto store_s = [&](){
        #pragma unroll
        for (int k = 0; k < 6; k++) {
            u64* dst = &sm.a.ws2[w_rr[k]*WP2 + w_cc[k]*4];
            float4 g = wreg[k];
            dst[0] = pack2(g.x, g.x);
            dst[1] = pack2(g.y, g.y);
            dst[2] = pack2(g.z, g.z);
            dst[3] = pack2(g.w, g.w);
        }
        #pragma unroll
        for (int k = 0; k < 4; k++)
            *(float4*)&sm.a.xs[x_mm[k]*XPAD + x_cc[k]*4] = xreg[k];
    };

    loadg(0); store_s();
    __syncthreads();

    // thread handles m-pairs p = 2k+mh  (m = 4k+2mh, 4k+2mh+1)
    const u64* wbase = &sm.a.ws2[r * WP2 + mh * 6];
    const int  xoff  = fg * 8;
    const int  xmh   = mh * 2 * XPAD;

    for (int t = 0; t < NTILE; t++) {
        if (t + 1 < NTILE) loadg(t + 1);

        #pragma unroll 4
        for (int k = 0; k < 16; k++) {
            const u64* wp = wbase + 12*k;
            ulonglong2 W0 = *(const ulonglong2*)(wp);       // (w_ma,j0) (w_ma,j1)
            ulonglong2 W1 = *(const ulonglong2*)(wp + 2);   // (w_ma,j2) (w_mb,j0)
            ulonglong2 W2 = *(const ulonglong2*)(wp + 4);   // (w_mb,j1) (w_mb,j2)
            const float* xrow = &sm.a.xs[4*k*XPAD + xmh + xoff];
            ulonglong2 a0 = *(const ulonglong2*)(xrow);
            ulonglong2 a1 = *(const ulonglong2*)(xrow + 4);
            ulonglong2 b0 = *(const ulonglong2*)(xrow + XPAD);
            ulonglong2 b1 = *(const ulonglong2*)(xrow + XPAD + 4);
            // m = ma
            acc[0][0] = fma2(W0.x, a0.x, acc[0][0]);
            acc[0][1] = fma2(W0.x, a0.y, acc[0][1]);
            acc[0][2] = fma2(W0.x, a1.x, acc[0][2]);
            acc[0][3] = fma2(W0.x, a1.y, acc[0][3]);
            acc[1][0] = fma2(W0.y, a0.x, acc[1][0]);
            acc[1][1] = fma2(W0.y, a0.y, acc[1][1]);
            acc[1][2] = fma2(W0.y, a1.x, acc[1][2]);
            acc[1][3] = fma2(W0.y, a1.y, acc[1][3]);
            acc[2][0] = fma2(W1.x, a0.x, acc[2][0]);
            acc[2][1] = fma2(W1.x, a0.y, acc[2][1]);
            acc[2][2] = fma2(W1.x, a1.x, acc[2][2]);
            acc[2][3] = fma2(W1.x, a1.y, acc[2][3]);
            // m = mb
            acc[0][0] = fma2(W1.y, b0.x, acc[0][0]);
            acc[0][1] = fma2(W1.y, b0.y, acc[0][1]);
            acc[0][2] = fma2(W1.y, b1.x, acc[0][2]);
            acc[0][3] = fma2(W1.y, b1.y, acc[0][3]);
            acc[1][0] = fma2(W2.x, b0.x, acc[1][0]);
            acc[1][1] = fma2(W2.x, b0.y, acc[1][1]);
            acc[1][2] = fma2(W2.x, b1.x, acc[1][2]);
            acc[1][3] = fma2(W2.x, b1.y, acc[1][3]);
            acc[2][0] = fma2(W2.y, b0.x, acc[2][0]);
            acc[2][1] = fma2(W2.y, b0.y, acc[2][1]);
            acc[2][2] = fma2(W2.y, b1.x, acc[2][2]);
            acc[2][3] = fma2(W2.y, b1.y, acc[2][3]);
        }
        __syncthreads();
        if (t + 1 < NTILE) { store_s(); __syncthreads(); }
    }

    // ============ epilogue: combine mh halves -> ys, FC, BN partials ============
    if (mh == 0) {
        #pragma unroll
        for (int j = 0; j < 3; j++)
            #pragma unroll
            for (int p = 0; p < 4; p++) {
                float lo, hi; unpack2(acc[j][p], lo, hi);
                sm.b.ys[r*96 + j*32 + fg*8 + p*2]     = lo;
                sm.b.ys[r*96 + j*32 + fg*8 + p*2 + 1] = hi;
            }
    }
    for (int i = tid; i < 64*96; i += 128) {
        int k = i / 96, c = i % 96;
        sm.b.wc[k*WCPAD + c] = (k < 32) ? W1[k*96 + c] : W2[(k-32)*96 + c];
    }
    if (tid < 32)       sm.b.bias[tid] = b1[tid];
    else if (tid < 64)  sm.b.bias[tid] = b2[tid - 32];
    __syncthreads();
    if (mh == 1) {
        #pragma unroll
        for (int j = 0; j < 3; j++)
            #pragma unroll
            for (int p = 0; p < 4; p++) {
                float lo, hi; unpack2(acc[j][p], lo, hi);
                sm.b.ys[r*96 + j*32 + fg*8 + p*2]     += lo;
                sm.b.ys[r*96 + j*32 + fg*8 + p*2 + 1] += hi;
            }
    }
    __syncthreads();

    {
        const int k  = tid & 63;
        const int rh = tid >> 6;          // 0/1
        float ls = 0.f, lsq = 0.f;
        const float bk = sm.b.bias[k];
        const u64* wk = (const u64*)&sm.b.wc[k * WCPAD];
        #pragma unroll 1
        for (int i = 0; i < 8; i++) {
            int row = rh + 2*i;
            const u64* yr = (const u64*)&sm.b.ys[row * 96];
            u64 a2 = 0ull;
            #pragma unroll
            for (int ii = 0; ii < 48; ii++) a2 = fma2(yr[ii], wk[ii], a2);
            float lo, hi; unpack2(a2, lo, hi);
            float z = lo + hi + bk;
            if (k < 32) z = fmaxf(z, 0.f);
            g_zbuf[(size_t)(R0 + row) * 64 + k] = z;
            ls  += z;
            lsq += z * z;
        }
        sm.b.psum[tid] = ls;
        sm.b.psq[tid]  = lsq;
    }
    __syncthreads();
    if (tid < 64) {
        g_part[cta*64 + tid] = sm.b.psum[tid] + sm.b.psum[tid + 64];
        g_psq[cta*64 + tid]  = sm.b.psq[tid]  + sm.b.psq[tid + 64];
    }
}

__global__ __launch_bounds__(128)
void k_stats(const float* __restrict__ gamma, const float* __restrict__ beta)
{
    __shared__ float rs[128], rq[128];
    const int k = blockIdx.x;
    const int tid = threadIdx.x;
    float s = 0.f, sq = 0.f;
    #pragma unroll
    for (int i = 0; i < NCTA/128; i++) {
        int c = tid + i*128;
        s  += g_part[c*64 + k];
        sq += g_psq[c*64 + k];
    }
    rs[tid] = s; rq[tid] = sq;
    __syncthreads();
    for (int off = 64; off >= 32; off >>= 1) {
        if (tid < off) { rs[tid] += rs[tid+off]; rq[tid] += rq[tid+off]; }
        __syncthreads();
    }
    if (tid < 32) {
        s = rs[tid]; sq = rq[tid];
        #pragma unroll
        for (int off = 16; off > 0; off >>= 1) {
            s  += __shfl_down_sync(0xffffffffu, s, off);
            sq += __shfl_down_sync(0xffffffffu, sq, off);
        }
        if (tid == 0) {
            float mean = s / (float)ROWS;
            float var  = sq / (float)ROWS - mean * mean;
            float sc = gamma[k] * rsqrtf(var + 1e-5f);
            g_scale[k] = sc;
            g_shift[k] = beta[k] - mean * sc;
        }
    }
}

__global__ __launch_bounds__(256)
void k_norm(float* __restrict__ out)
{
    __shared__ float sc[64], sh[64];
    int tid = threadIdx.x;
    if (tid < 64) { sc[tid] = g_scale[tid]; sh[tid] = g_shift[tid]; }
    __syncthreads();
    int i = blockIdx.x * 256 + tid;                 // float4 index, 131072 total
    float4 z = ((const float4*)g_zbuf)[i];
    int kb = (i & 15) * 4;
    float4 o;
    o.x = z.x * sc[kb+0] + sh[kb+0];
    o.y = z.y * sc[kb+1] + sh[kb+1];
    o.z = z.z * sc[kb+2] + sh[kb+2];
    o.w = z.w * sc[kb+3] + sh[kb+3];
    ((float4*)out)[i] = o;
}

extern "C" void kernel_launch(void* const* d_in, const int* in_sizes, int n_in,
                              void* d_out, int out_size)
{
    const float* WW    = (const float*)d_in[0];
    const float* x     = (const float*)d_in[1];
    const float* W1    = (const float*)d_in[2];
    const float* b1    = (const float*)d_in[3];
    const float* W2    = (const float*)d_in[4];
    const float* b2    = (const float*)d_in[5];
    const float* gamma = (const float*)d_in[6];
    const float* beta  = (const float*)d_in[7];
    float* out = (float*)d_out;

    k_main <<<NCTA, 128>>>(WW, x, W1, b1, W2, b2);
    k_stats<<<64, 128>>>(gamma, beta);
    k_norm <<<ROWS*64/(256*4), 256>>>(out);
}

// round 5
// speedup vs baseline: 1.4489x; 1.4489x over previous
#include <cuda_runtime.h>
#include <cstdint>

#define BS   8
#define NN   1024
#define JJ   3
#define FIN  32
#define ROWS (BS*NN)        // 8192
#define RPC  16             // rows per CTA
#define NCTA (ROWS/RPC)     // 512
#define MT   64             // m per tile
#define NTILE (NN/MT)       // 16
#define WSF  (RPC*192)      // ws floats per buffer (3072)
#define XSF  (MT*32)        // xs floats per buffer (2048)
#define WCPAD 98

typedef unsigned long long u64;

// scratch (no allocations allowed)
__device__ float g_zbuf[ROWS*64];
__device__ float g_part[NCTA*64];
__device__ float g_psq[NCTA*64];
__device__ float g_scale[64];
__device__ float g_shift[64];

__device__ __forceinline__ u64 pack2(float a, float b){
    u64 r; asm("mov.b64 %0,{%1,%2};" : "=l"(r) : "f"(a), "f"(b)); return r;
}
__device__ __forceinline__ void unpack2(u64 v, float& a, float& b){
    asm("mov.b64 {%0,%1},%2;" : "=f"(a), "=f"(b) : "l"(v));
}
__device__ __forceinline__ u64 fma2(u64 a, u64 b, u64 c){
    u64 d; asm("fma.rn.f32x2 %0,%1,%2,%3;" : "=l"(d) : "l"(a), "l"(b), "l"(c)); return d;
}
__device__ __forceinline__ void cp16(float* smem_dst, const float4* gsrc){
    unsigned s = (unsigned)__cvta_generic_to_shared(smem_dst);
    asm volatile("cp.async.cg.shared.global [%0], [%1], 16;" :: "r"(s), "l"(gsrc));
}

struct SmemA {                        // main loop, double buffered
    float ws[2][WSF];                 // 24576 B : plain fp32, [rr][cc^swz], 16B-swizzled
    float xs[2][XSF];                 // 16384 B : [m][f]
};
struct SmemB {                        // epilogue
    float ys[RPC*96];                 // 6144 B
    float wc[64*WCPAD];               // 25088 B
    float bias[64];
    float psum[128];
    float psq[128];
};
union __align__(16) SmemU { SmemA a; SmemB b; };   // 40960 B

// 12 FFMA2 for one (row, m): 3 j's into acc[rsel][j][0..3]
__device__ __forceinline__ void mstep(u64 acc[2][3][4], int rsel,
                                      float wj0, float wj1, float wj2,
                                      ulonglong2 xa, ulonglong2 xb)
{
    u64 W0 = pack2(wj0, wj0), W1 = pack2(wj1, wj1), W2 = pack2(wj2, wj2);
    acc[rsel][0][0] = fma2(W0, xa.x, acc[rsel][0][0]);
    acc[rsel][0][1] = fma2(W0, xa.y, acc[rsel][0][1]);
    acc[rsel][0][2] = fma2(W0, xb.x, acc[rsel][0][2]);
    acc[rsel][0][3] = fma2(W0, xb.y, acc[rsel][0][3]);
    acc[rsel][1][0] = fma2(W1, xa.x, acc[rsel][1][0]);
    acc[rsel][1][1] = fma2(W1, xa.y, acc[rsel][1][1]);
    acc[rsel][1][2] = fma2(W1, xb.x, acc[rsel][1][2]);
    acc[rsel][1][3] = fma2(W1, xb.y, acc[rsel][1][3]);
    acc[rsel][2][0] = fma2(W2, xa.x, acc[rsel][2][0]);
    acc[rsel][2][1] = fma2(W2, xa.y, acc[rsel][2][1]);
    acc[rsel][2][2] = fma2(W2, xb.x, acc[rsel][2][2]);
    acc[rsel][2][3] = fma2(W2, xb.y, acc[rsel][2][3]);
}

__global__ __launch_bounds__(128, 4)
void k_main(const float* __restrict__ WW, const float* __restrict__ x,
            const float* __restrict__ W1, const float* __restrict__ b1,
            const float* __restrict__ W2, const float* __restrict__ b2)
{
    __shared__ SmemU sm;
    const int tid  = threadIdx.x;
    const int cta  = blockIdx.x;
    const int R0   = cta * RPC;
    const int bb   = R0 / NN;

    const int lane = tid & 31;
    const int warp = tid >> 5;        // q = m-quarter (warp-uniform)
    const int q    = warp;
    const int fg   = lane & 3;        // f-group of 8
    const int rp   = lane >> 2;       // row-pair 0..7  (rows 2rp, 2rp+1)

    u64 acc[2][3][4];
    #pragma unroll
    for (int rs = 0; rs < 2; rs++)
        #pragma unroll
        for (int j = 0; j < 3; j++)
            #pragma unroll
            for (int p = 0; p < 4; p++) acc[rs][j][p] = 0ull;

    const float* xb = x + (size_t)bb * NN * FIN;

    // tile-invariant cp.async assignments
    int w_rr[6], w_cs[6];             // src col cc, dst col cc^(rr>>1)
    int w_cd[6];
    #pragma unroll
    for (int k = 0; k < 6; k++) {
        int idx = tid + k*128;        // 0..767
        w_rr[k] = idx / 48;
        w_cs[k] = idx % 48;
        w_cd[k] = w_cs[k] ^ (w_rr[k] >> 1);
    }
    int x_mm[4], x_cc[4];
    #pragma unroll
    for (int k = 0; k < 4; k++) { int idx = tid + k*128; x_mm[k] = idx >> 3; x_cc[k] = idx & 7; }

    auto issue = [&](int t){
        const int m0 = t * MT;
        const int buf = t & 1;
        #pragma unroll
        for (int k = 0; k < 6; k++) {
            const float4* src = (const float4*)(WW + ((size_t)(R0 + w_rr[k]) * NN + m0) * JJ) + w_cs[k];
            cp16(&sm.a.ws[buf][w_rr[k]*192 + w_cd[k]*4], src);
        }
        #pragma unroll
        for (int k = 0; k < 4; k++) {
            const float4* src = (const float4*)(xb + (size_t)(m0 + x_mm[k]) * FIN) + x_cc[k];
            cp16(&sm.a.xs[buf][x_mm[k]*32 + x_cc[k]*4], src);
        }
        asm volatile("cp.async.commit_group;" ::: "memory");
    };

    issue(0);

    const int wr0 = (2*rp)   * 192;
    const int wr1 = (2*rp+1) * 192;
    const int xcol = fg * 8;

    #pragma unroll 1
    for (int t = 0; t < NTILE; t++) {
        if (t + 1 < NTILE) {
            issue(t + 1);
            asm volatile("cp.async.wait_group 1;" ::: "memory");
        } else {
            asm volatile("cp.async.wait_group 0;" ::: "memory");
        }
        __syncthreads();

        const float* wsb = sm.a.ws[t & 1];
        const float* xsb = sm.a.xs[t & 1];

        #pragma unroll
        for (int k4 = 0; k4 < 4; k4++) {
            const int cc0 = 12*q + 3*k4;                 // float4 col base
            float4 A0 = *(const float4*)&wsb[wr0 + ((cc0+0)^rp)*4];
            float4 A1 = *(const float4*)&wsb[wr0 + ((cc0+1)^rp)*4];
            float4 A2 = *(const float4*)&wsb[wr0 + ((cc0+2)^rp)*4];
            float4 B0 = *(const float4*)&wsb[wr1 + ((cc0+0)^rp)*4];
            float4 B1 = *(const float4*)&wsb[wr1 + ((cc0+1)^rp)*4];
            float4 B2 = *(const float4*)&wsb[wr1 + ((cc0+2)^rp)*4];
            const float* xrow = xsb + (16*q + 4*k4)*32 + xcol;
            ulonglong2 x0a = *(const ulonglong2*)(xrow);
            ulonglong2 x0b = *(const ulonglong2*)(xrow + 4);
            ulonglong2 x1a = *(const ulonglong2*)(xrow + 32);
            ulonglong2 x1b = *(const ulonglong2*)(xrow + 36);
            ulonglong2 x2a = *(const ulonglong2*)(xrow + 64);
            ulonglong2 x2b = *(const ulonglong2*)(xrow + 68);
            ulonglong2 x3a = *(const ulonglong2*)(xrow + 96);
            ulonglong2 x3b = *(const ulonglong2*)(xrow + 100);
            // row 2rp:   m+0..3  (w per m: 3 consecutive floats)
            mstep(acc, 0, A0.x, A0.y, A0.z, x0a, x0b);
            mstep(acc, 0, A0.w, A1.x, A1.y, x1a, x1b);
            mstep(acc, 0, A1.z, A1.w, A2.x, x2a, x2b);
            mstep(acc, 0, A2.y, A2.z, A2.w, x3a, x3b);
            // row 2rp+1
            mstep(acc, 1, B0.x, B0.y, B0.z, x0a, x0b);
            mstep(acc, 1, B0.w, B1.x, B1.y, x1a, x1b);
            mstep(acc, 1, B1.z, B1.w, B2.x, x2a, x2b);
            mstep(acc, 1, B2.y, B2.z, B2.w, x3a, x3b);
        }
        __syncthreads();
    }

    // ============ epilogue: 4-warp combine -> ys, FC, BN partials ============
    // overlap: wc/bias LDGs issued by all threads while ys phases serialize
    for (int i = tid; i < 64*96; i += 128) {
        int k = i / 96, c = i % 96;
        sm.b.wc[k*WCPAD + c] = (k < 32) ? W1[k*96 + c] : W2[(k-32)*96 + c];
    }
    if (tid < 32)       sm.b.bias[tid] = b1[tid];
    else if (tid < 64)  sm.b.bias[tid] = b2[tid - 32];

    #pragma unroll 1
    for (int ph = 0; ph < 4; ph++) {
        if (warp == ph) {
            #pragma unroll
            for (int rs = 0; rs < 2; rs++)
                #pragma unroll
                for (int j = 0; j < 3; j++)
                    #pragma unroll
                    for (int p = 0; p < 4; p++) {
                        float lo, hi; unpack2(acc[rs][j][p], lo, hi);
                        int row = 2*rp + rs;
                        int col = j*32 + fg*8 + 2*p;
                        if (ph == 0) {
                            sm.b.ys[row*96 + col]     = lo;
                            sm.b.ys[row*96 + col + 1] = hi;
                        } else {
                            sm.b.ys[row*96 + col]     += lo;
                            sm.b.ys[row*96 + col + 1] += hi;
                        }
                    }
        }
        __syncthreads();
    }

    {
        const int k  = tid & 63;
        const int rh = tid >> 6;          // 0/1
        float ls = 0.f, lsq = 0.f;
        const float bk = sm.b.bias[k];
        const u64* wk = (const u64*)&sm.b.wc[k * WCPAD];
        #pragma unroll 1
        for (int i = 0; i < 8; i++) {
            int row = rh + 2*i;
            const u64* yr = (const u64*)&sm.b.ys[row * 96];
            u64 a2 = 0ull;
            #pragma unroll
            for (int ii = 0; ii < 48; ii++) a2 = fma2(yr[ii], wk[ii], a2);
            float lo, hi; unpack2(a2, lo, hi);
            float z = lo + hi + bk;
            if (k < 32) z = fmaxf(z, 0.f);
            g_zbuf[(size_t)(R0 + row) * 64 + k] = z;
            ls  += z;
            lsq += z * z;
        }
        sm.b.psum[tid] = ls;
        sm.b.psq[tid]  = lsq;
    }
    __syncthreads();
    if (tid < 64) {
        g_part[cta*64 + tid] = sm.b.psum[tid] + sm.b.psum[tid + 64];
        g_psq[cta*64 + tid]  = sm.b.psq[tid]  + sm.b.psq[tid + 64];
    }
}

__global__ __launch_bounds__(128)
void k_stats(const float* __restrict__ gamma, const float* __restrict__ beta)
{
    __shared__ float rs[128], rq[128];
    const int k = blockIdx.x;
    const int tid = threadIdx.x;
    float s = 0.f, sq = 0.f;
    #pragma unroll
    for (int i = 0; i < NCTA/128; i++) {
        int c = tid + i*128;
        s  += g_part[c*64 + k];
        sq += g_psq[c*64 + k];
    }
    rs[tid] = s; rq[tid] = sq;
    __syncthreads();
    for (int off = 64; off >= 32; off >>= 1) {
        if (tid < off) { rs[tid] += rs[tid+off]; rq[tid] += rq[tid+off]; }
        __syncthreads();
    }
    if (tid < 32) {
        s = rs[tid]; sq = rq[tid];
        #pragma unroll
        for (int off = 16; off > 0; off >>= 1) {
            s  += __shfl_down_sync(0xffffffffu, s, off);
            sq += __shfl_down_sync(0xffffffffu, sq, off);
        }
        if (tid == 0) {
            float mean = s / (float)ROWS;
            float var  = sq / (float)ROWS - mean * mean;
            float sc = gamma[k] * rsqrtf(var + 1e-5f);
            g_scale[k] = sc;
            g_shift[k] = beta[k] - mean * sc;
        }
    }
}

__global__ __launch_bounds__(256)
void k_norm(float* __restrict__ out)
{
    __shared__ float sc[64], sh[64];
    int tid = threadIdx.x;
    if (tid < 64) { sc[tid] = g_scale[tid]; sh[tid] = g_shift[tid]; }
    __syncthreads();
    int i = blockIdx.x * 256 + tid;                 // float4 index, 131072 total
    float4 z = ((const float4*)g_zbuf)[i];
    int kb = (i & 15) * 4;
    float4 o;
    o.x = z.x * sc[kb+0] + sh[kb+0];
    o.y = z.y * sc[kb+1] + sh[kb+1];
    o.z = z.z * sc[kb+2] + sh[kb+2];
    o.w = z.w * sc[kb+3] + sh[kb+3];
    ((float4*)out)[i] = o;
}

extern "C" void kernel_launch(void* const* d_in, const int* in_sizes, int n_in,
                              void* d_out, int out_size)
{
    const float* WW    = (const float*)d_in[0];
    const float* x     = (const float*)d_in[1];
    const float* W1    = (const float*)d_in[2];
    const float* b1    = (const float*)d_in[3];
    const float* W2    = (const float*)d_in[4];
    const float* b2    = (const float*)d_in[5];
    const float* gamma = (const float*)d_in[6];
    const float* beta  = (const float*)d_in[7];
    float* out = (float*)d_out;

    k_main <<<NCTA, 128>>>(WW, x, W1, b1, W2, b2);
    k_stats<<<64, 128>>>(gamma, beta);
    k_norm <<<ROWS*64/(256*4), 256>>>(out);
}